// round 14
// baseline (speedup 1.0000x reference)
#include <cuda_runtime.h>
#include <cuda_bf16.h>
#include <cstdint>

#define NB 4096
#define NN 8192
#define DD 128
#define MT 64
#define NT 64
#define SPAD 144     // bytes per 128-byte int8 row (+16B pad) -> conflict-free

__device__ int8_t g_znq[NN * DD];           // int8 quantized normalized rows (x127)
__device__ float g_Srow2[2][NN];            // register-acc row partials (per d-half)
__device__ float g_colh[2][64][NN];         // column-sum partials [wm][d-1][col]
__device__ float g_pos[NN];                 // per-row positive-pair sim (fp32, exact)
__device__ double g_part[256];              // partial sums for final reduction

// ------- kernel 1: fused normalize + int8 quantize + positive-pair -----------
__global__ void __launch_bounds__(256) k_prep(const float* __restrict__ zi,
                                              const float* __restrict__ zj) {
    int wid = threadIdx.x >> 5, lane = threadIdx.x & 31;
    int i = blockIdx.x * 8 + wid;           // pair index in [0, NB)
    float4 a = ((const float4*)(zi + (size_t)i * DD))[lane];
    float4 b = ((const float4*)(zj + (size_t)i * DD))[lane];
    float na = a.x * a.x + a.y * a.y + a.z * a.z + a.w * a.w;
    float nb = b.x * b.x + b.y * b.y + b.z * b.z + b.w * b.w;
    float dd = a.x * b.x + a.y * b.y + a.z * b.z + a.w * b.w;
    #pragma unroll
    for (int o = 16; o; o >>= 1) {
        na += __shfl_xor_sync(0xffffffffu, na, o);
        nb += __shfl_xor_sync(0xffffffffu, nb, o);
        dd += __shfl_xor_sync(0xffffffffu, dd, o);
    }
    float rna = 127.0f / fmaxf(sqrtf(na), 1e-8f);
    float rnb = 127.0f / fmaxf(sqrtf(nb), 1e-8f);

    int q0 = __float2int_rn(a.x * rna), q1 = __float2int_rn(a.y * rna);
    int q2 = __float2int_rn(a.z * rna), q3 = __float2int_rn(a.w * rna);
    uint32_t pa = (uint32_t)(q0 & 0xFF) | ((uint32_t)(q1 & 0xFF) << 8) |
                  ((uint32_t)(q2 & 0xFF) << 16) | ((uint32_t)(q3 & 0xFF) << 24);
    q0 = __float2int_rn(b.x * rnb); q1 = __float2int_rn(b.y * rnb);
    q2 = __float2int_rn(b.z * rnb); q3 = __float2int_rn(b.w * rnb);
    uint32_t pb = (uint32_t)(q0 & 0xFF) | ((uint32_t)(q1 & 0xFF) << 8) |
                  ((uint32_t)(q2 & 0xFF) << 16) | ((uint32_t)(q3 & 0xFF) << 24);

    ((uint32_t*)(g_znq + (size_t)i * DD))[lane] = pa;
    ((uint32_t*)(g_znq + (size_t)(i + NB) * DD))[lane] = pb;

    if (lane == 0) {
        float s = 2.0f * dd * (rna / 127.0f) * (rnb / 127.0f) * (127.0f * 127.0f)
                  / (127.0f * 127.0f);               // = 2*cos, fp32 exact path
        s = 2.0f * dd / (fmaxf(sqrtf(na), 1e-8f) * fmaxf(sqrtf(nb), 1e-8f));
        g_pos[i] = s;
        g_pos[i + NB] = s;
    }
}

// ---------------- PTX helpers ------------------------------------------------
__device__ __forceinline__ void mma_s8(int d[4], const uint32_t a[4],
                                       uint32_t b0, uint32_t b1) {
    asm volatile(
        "mma.sync.aligned.m16n8k32.row.col.s32.s8.s8.s32 "
        "{%0,%1,%2,%3}, {%4,%5,%6,%7}, {%8,%9}, {%0,%1,%2,%3};\n"
        : "+r"(d[0]), "+r"(d[1]), "+r"(d[2]), "+r"(d[3])
        : "r"(a[0]), "r"(a[1]), "r"(a[2]), "r"(a[3]), "r"(b0), "r"(b1));
}

__device__ __forceinline__ void ldmx4(uint32_t& r0, uint32_t& r1,
                                      uint32_t& r2, uint32_t& r3, uint32_t addr) {
    asm volatile("ldmatrix.sync.aligned.m8n8.x4.shared.b16 {%0,%1,%2,%3}, [%4];"
                 : "=r"(r0), "=r"(r1), "=r"(r2), "=r"(r3) : "r"(addr));
}

__device__ __forceinline__ void cp_async16(uint32_t saddr, const void* gaddr) {
    asm volatile("cp.async.ca.shared.global [%0], [%1], 16;\n"
                 :: "r"(saddr), "l"(gaddr));
}
__device__ __forceinline__ void cp_commit() {
    asm volatile("cp.async.commit_group;\n");
}
template <int N>
__device__ __forceinline__ void cp_wait() {
    asm volatile("cp.async.wait_group %0;\n" :: "n"(N));
}

__device__ __forceinline__ float ex2f(float x) {
    float y;
    asm("ex2.approx.ftz.f32 %0, %1;" : "=f"(y) : "f"(x));
    return y;
}

// exp(2c - 2) = exp2(dot * C2/127^2 - C2), dot = 127^2 * c (exact int)
#define C2  2.8853900817779268f
#define SC2 (2.8853900817779268f / 16129.0f)

// -------- kernel 2: symmetric tile sweep, int8 tensor cores ------------------
// Wrapped diagonals: tile (I, (I+d)%128), d in [0,64] (d=64 only for I<64).
// Row-sums -> block I (registers), col-sums -> unique slots g_colh[wm][d-1][col].
// 256 CTAs = (I, half). 2 CTAs/SM.
__global__ void __launch_bounds__(256, 2) k_simexp() {
    __shared__ __align__(16) int8_t As[MT * SPAD];
    __shared__ __align__(16) int8_t Bs[2][NT * SPAD];
    __shared__ float sp[MT][16];

    const int tid = threadIdx.x;
    const int lane = tid & 31, wid = tid >> 5;
    const int g = lane >> 2, i4 = lane & 3;
    const int wm = wid & 1, wn = wid >> 1;          // wn in 0..3
    const int I = blockIdx.x >> 1;
    const int h = blockIdx.x & 1;
    const int m0 = I * MT;
    const int dstart = h ? 33 : 0;
    const int dend = h ? ((I < 64) ? 64 : 63) : 32;   // inclusive

    // ---- stage A rows (64 x 128B) into padded smem ----
    #pragma unroll
    for (int p = 0; p < 2; ++p) {
        int c = tid + p * 256;                  // 512 16B chunks
        int r = c >> 3, cc = c & 7;
        *(uint4*)&As[r * SPAD + cc * 16] =
            *(const uint4*)(g_znq + (size_t)(m0 + r) * DD + cc * 16);
    }

    uint32_t bbase[2];
    bbase[0] = (uint32_t)__cvta_generic_to_shared(&Bs[0][0]);
    bbase[1] = (uint32_t)__cvta_generic_to_shared(&Bs[1][0]);

    // prologue: prefetch first tile into buf 0
    {
        const int j0 = ((I + dstart) & 127) * MT;
        #pragma unroll
        for (int p = 0; p < 2; ++p) {
            int c = tid + p * 256;
            int r = c >> 3, cc = c & 7;
            cp_async16(bbase[0] + (uint32_t)(r * SPAD + cc * 16),
                       g_znq + (size_t)(j0 + r) * DD + cc * 16);
        }
        cp_commit();
    }
    __syncthreads();   // As visible

    // ---- hoist A fragments to registers: 4 ks x 2 mt x 4 regs (32 regs) ----
    uint32_t areg[4][2][4];
    #pragma unroll
    for (int ks = 0; ks < 4; ++ks) {
        const int kb = ks * 32 + 4 * i4;
        #pragma unroll
        for (int mt = 0; mt < 2; ++mt) {
            const int r0 = wm * 32 + mt * 16;
            areg[ks][mt][0] = *(const uint32_t*)&As[(r0 + g) * SPAD + kb];
            areg[ks][mt][1] = *(const uint32_t*)&As[(r0 + g + 8) * SPAD + kb];
            areg[ks][mt][2] = *(const uint32_t*)&As[(r0 + g) * SPAD + kb + 16];
            areg[ks][mt][3] = *(const uint32_t*)&As[(r0 + g + 8) * SPAD + kb + 16];
        }
    }

    // ldmatrix lane base: m0=(cb0,k0-15) m1=(cb0,k16-31) m2=(cb1,k0-15) m3=(cb1,k16-31)
    const int l8 = lane & 7;
    const int rowb = wn * 16 + ((lane >> 4) & 1) * 8 + l8;
    const int koff = ((lane >> 3) & 1) * 16;
    const uint32_t ldm_off = (uint32_t)(rowb * SPAD + koff);

    float acc[2][2] = {{0.f, 0.f}, {0.f, 0.f}};

    for (int d = dstart; d <= dend; ++d) {
        const int buf = (d - dstart) & 1;
        cp_wait<0>();
        __syncthreads();   // B[buf] visible; all warps done reading buf^1

        // prefetch next tile; overlaps this tile's compute
        if (d + 1 <= dend) {
            const int j1 = ((I + d + 1) & 127) * MT;
            #pragma unroll
            for (int p = 0; p < 2; ++p) {
                int c = tid + p * 256;
                int r = c >> 3, cc = c & 7;
                cp_async16(bbase[buf ^ 1] + (uint32_t)(r * SPAD + cc * 16),
                           g_znq + (size_t)(j1 + r) * DD + cc * 16);
            }
            cp_commit();
        }

        int cd[2][2][4];
        #pragma unroll
        for (int mt = 0; mt < 2; ++mt)
            #pragma unroll
            for (int nt = 0; nt < 2; ++nt)
                #pragma unroll
                for (int q = 0; q < 4; ++q) cd[mt][nt][q] = 0;

        const uint32_t bb = bbase[buf] + ldm_off;
        #pragma unroll
        for (int ks = 0; ks < 4; ++ks) {
            uint32_t b0, b1, b2, b3;
            ldmx4(b0, b1, b2, b3, bb + (uint32_t)ks * 32);
            mma_s8(cd[0][0], areg[ks][0], b0, b1);
            mma_s8(cd[1][0], areg[ks][1], b0, b1);
            mma_s8(cd[0][1], areg[ks][0], b2, b3);
            mma_s8(cd[1][1], areg[ks][1], b2, b3);
        }

        const int j0 = ((I + d) & 127) * MT;
        if (d != 0) {
            // off-diagonal: exp + row acc + column partial sums
            float cs0[2] = {0.f, 0.f}, cs1[2] = {0.f, 0.f};
            #pragma unroll
            for (int mt = 0; mt < 2; ++mt)
                #pragma unroll
                for (int nt = 0; nt < 2; ++nt) {
                    float e0 = ex2f(fmaf((float)cd[mt][nt][0], SC2, -C2));
                    float e1 = ex2f(fmaf((float)cd[mt][nt][1], SC2, -C2));
                    float e2 = ex2f(fmaf((float)cd[mt][nt][2], SC2, -C2));
                    float e3 = ex2f(fmaf((float)cd[mt][nt][3], SC2, -C2));
                    acc[mt][0] += e0 + e1;
                    acc[mt][1] += e2 + e3;
                    cs0[nt] += e0 + e2;
                    cs1[nt] += e1 + e3;
                }
            // reduce column partials over g (lanes stride 4)
            #pragma unroll
            for (int nt = 0; nt < 2; ++nt) {
                #pragma unroll
                for (int o = 4; o <= 16; o <<= 1) {
                    cs0[nt] += __shfl_xor_sync(0xffffffffu, cs0[nt], o);
                    cs1[nt] += __shfl_xor_sync(0xffffffffu, cs1[nt], o);
                }
            }
            if (g == 0) {   // lanes 0..3 hold totals; direct float2 store
                #pragma unroll
                for (int nt = 0; nt < 2; ++nt) {
                    const int C = wn * 16 + nt * 8 + 2 * i4;
                    float2 v = make_float2(cs0[nt], cs1[nt]);
                    *(float2*)&g_colh[wm][d - 1][j0 + C] = v;
                }
            }
        } else {
            // diagonal tile: row sums only, mask i==j exactly
            #pragma unroll
            for (int mt = 0; mt < 2; ++mt) {
                const int R = m0 + wm * 32 + mt * 16 + g;
                #pragma unroll
                for (int nt = 0; nt < 2; ++nt) {
                    const int C = j0 + wn * 16 + nt * 8 + 2 * i4;
                    float e0 = (R     == C    ) ? 0.f : ex2f(fmaf((float)cd[mt][nt][0], SC2, -C2));
                    float e1 = (R     == C + 1) ? 0.f : ex2f(fmaf((float)cd[mt][nt][1], SC2, -C2));
                    float e2 = (R + 8 == C    ) ? 0.f : ex2f(fmaf((float)cd[mt][nt][2], SC2, -C2));
                    float e3 = (R + 8 == C + 1) ? 0.f : ex2f(fmaf((float)cd[mt][nt][3], SC2, -C2));
                    acc[mt][0] += e0 + e1;
                    acc[mt][1] += e2 + e3;
                }
            }
        }
    }

    // deterministic cross-thread reduction of register row partials
    __syncthreads();
    #pragma unroll
    for (int mt = 0; mt < 2; ++mt) {
        sp[wm * 32 + mt * 16 + g    ][wn * 4 + i4] = acc[mt][0];
        sp[wm * 32 + mt * 16 + g + 8][wn * 4 + i4] = acc[mt][1];
    }
    __syncthreads();
    if (tid < MT) {
        float s = 0.f;
        #pragma unroll
        for (int k = 0; k < 16; ++k) s += sp[tid][k];
        g_Srow2[h][m0 + tid] = s;
    }
}

// ---------------- kernel 3: assemble row sums, high-MLP ----------------------
// 256 blocks x 256 threads; 32 rows/block; 8 d-groups of 8 slots each.
__global__ void __launch_bounds__(256) k_final1() {
    __shared__ float sredf[8][32];
    const int tid = threadIdx.x;
    const int r = tid & 31;          // row within block (coalesced)
    const int q = tid >> 5;          // 0..7 (d-group)
    const int row = blockIdx.x * 32 + r;

    float s = 0.f;
    const int d0 = q * 8;
    #pragma unroll
    for (int k = 0; k < 8; ++k) {
        int d = d0 + k;
        if (d < 63) s += g_colh[0][d][row] + g_colh[1][d][row];
    }
    if (q == 7 && row >= NB) s += g_colh[0][63][row] + g_colh[1][63][row];
    if (q == 0) s += g_Srow2[0][row] + g_Srow2[1][row];
    sredf[q][r] = s;
    __syncthreads();

    if (tid < 32) {
        float S = 0.f;
        #pragma unroll
        for (int k = 0; k < 8; ++k) S += sredf[k][tid];
        int rw = blockIdx.x * 32 + tid;
        double t = 2.0 + (double)logf(S) - (double)g_pos[rw];
        #pragma unroll
        for (int o = 16; o; o >>= 1)
            t += __shfl_xor_sync(0xffffffffu, t, o);
        if (tid == 0) g_part[blockIdx.x] = t;
    }
}

// ---------------- kernel 4: final combine ------------------------------------
__global__ void __launch_bounds__(32) k_final2(float* out) {
    int tid = threadIdx.x;
    double t = 0.0;
    #pragma unroll
    for (int k = 0; k < 8; ++k) t += g_part[tid + 32 * k];
    #pragma unroll
    for (int o = 16; o; o >>= 1)
        t += __shfl_xor_sync(0xffffffffu, t, o);
    if (tid == 0) out[0] = (float)(t / (double)NN);
}

extern "C" void kernel_launch(void* const* d_in, const int* in_sizes, int n_in,
                              void* d_out, int out_size) {
    const float* zi = (const float*)d_in[0];
    const float* zj = (const float*)d_in[1];
    float* out = (float*)d_out;
    (void)in_sizes; (void)n_in; (void)out_size;

    k_prep<<<NB / 8, 256>>>(zi, zj);
    k_simexp<<<256, 256>>>();
    k_final1<<<256, 256>>>();
    k_final2<<<1, 32>>>(out);
}

// round 15
// speedup vs baseline: 2.0375x; 2.0375x over previous
#include <cuda_runtime.h>
#include <cuda_bf16.h>
#include <cstdint>

#define NB 4096
#define NN 8192
#define DD 128
#define MT 64
#define NT 64
#define SPAD 136     // 128 + 8 bf16 pad (272B row stride) -> conflict-free ldmatrix

__device__ __nv_bfloat16 g_znb[NN * DD];    // bf16 normalized rows
__device__ float g_Srow2[2][NN];            // register-acc row partials (per d-half)
__device__ float g_colh[2][64][NN];         // column-sum partials [wm][d-1][col]
__device__ float g_pos[NN];                 // per-row positive-pair sim (fp32)
__device__ double g_part[512];              // partial sums for final reduction

// ------- kernel 1: fused normalize(+bf16) + positive-pair (exact fp32) -------
__global__ void __launch_bounds__(256) k_prep(const float* __restrict__ zi,
                                              const float* __restrict__ zj) {
    int wid = threadIdx.x >> 5, lane = threadIdx.x & 31;
    int i = blockIdx.x * 8 + wid;           // pair index in [0, NB)
    float4 a = ((const float4*)(zi + (size_t)i * DD))[lane];
    float4 b = ((const float4*)(zj + (size_t)i * DD))[lane];
    float na = a.x * a.x + a.y * a.y + a.z * a.z + a.w * a.w;
    float nb = b.x * b.x + b.y * b.y + b.z * b.z + b.w * b.w;
    float dd = a.x * b.x + a.y * b.y + a.z * b.z + a.w * b.w;
    #pragma unroll
    for (int o = 16; o; o >>= 1) {
        na += __shfl_xor_sync(0xffffffffu, na, o);
        nb += __shfl_xor_sync(0xffffffffu, nb, o);
        dd += __shfl_xor_sync(0xffffffffu, dd, o);
    }
    float sa = fmaxf(sqrtf(na), 1e-8f);
    float sb = fmaxf(sqrtf(nb), 1e-8f);
    float rna = 1.0f / sa, rnb = 1.0f / sb;
    {
        __nv_bfloat162* d0 = (__nv_bfloat162*)(g_znb + (size_t)i * DD + lane * 4);
        d0[0] = __floats2bfloat162_rn(a.x * rna, a.y * rna);
        d0[1] = __floats2bfloat162_rn(a.z * rna, a.w * rna);
        __nv_bfloat162* d1 = (__nv_bfloat162*)(g_znb + (size_t)(i + NB) * DD + lane * 4);
        d1[0] = __floats2bfloat162_rn(b.x * rnb, b.y * rnb);
        d1[1] = __floats2bfloat162_rn(b.z * rnb, b.w * rnb);
    }
    if (lane == 0) {
        float s = 2.0f * dd * rna * rnb;    // cos / TEMP, exact fp32 path
        g_pos[i] = s;
        g_pos[i + NB] = s;
    }
}

// ---------------- PTX helpers ------------------------------------------------
__device__ __forceinline__ void mma_bf16(float d[4], const uint32_t a[4],
                                         uint32_t b0, uint32_t b1) {
    asm volatile(
        "mma.sync.aligned.m16n8k16.row.col.f32.bf16.bf16.f32 "
        "{%0,%1,%2,%3}, {%4,%5,%6,%7}, {%8,%9}, {%0,%1,%2,%3};\n"
        : "+f"(d[0]), "+f"(d[1]), "+f"(d[2]), "+f"(d[3])
        : "r"(a[0]), "r"(a[1]), "r"(a[2]), "r"(a[3]), "r"(b0), "r"(b1));
}

__device__ __forceinline__ void ldmx4(uint32_t& r0, uint32_t& r1,
                                      uint32_t& r2, uint32_t& r3, uint32_t addr) {
    asm volatile("ldmatrix.sync.aligned.m8n8.x4.shared.b16 {%0,%1,%2,%3}, [%4];"
                 : "=r"(r0), "=r"(r1), "=r"(r2), "=r"(r3) : "r"(addr));
}

__device__ __forceinline__ void cp_async16(uint32_t saddr, const void* gaddr) {
    asm volatile("cp.async.ca.shared.global [%0], [%1], 16;\n"
                 :: "r"(saddr), "l"(gaddr));
}
__device__ __forceinline__ void cp_commit() {
    asm volatile("cp.async.commit_group;\n");
}
template <int N>
__device__ __forceinline__ void cp_wait() {
    asm volatile("cp.async.wait_group %0;\n" :: "n"(N));
}

__device__ __forceinline__ float ex2f(float x) {
    float y;
    asm("ex2.approx.ftz.f32 %0, %1;" : "=f"(y) : "f"(x));
    return y;
}

// 2*log2(e): exp(2c-2) = exp2(c*C2 - C2)
#define C2 2.8853900817779268f

// -------- kernel 2: symmetric tile sweep (identical to the 45.15us R11) ------
__global__ void __launch_bounds__(256, 2) k_simexp() {
    __shared__ __align__(16) __nv_bfloat16 As[MT * SPAD];
    __shared__ __align__(16) __nv_bfloat16 Bs[2][NT * SPAD];
    __shared__ float sp[MT][16];

    const int tid = threadIdx.x;
    const int lane = tid & 31, wid = tid >> 5;
    const int g = lane >> 2, i4 = lane & 3;
    const int wm = wid & 1, wn = wid >> 1;          // wn in 0..3
    const int I = blockIdx.x >> 1;
    const int h = blockIdx.x & 1;
    const int m0 = I * MT;
    const int dstart = h ? 33 : 0;
    const int dend = h ? ((I < 64) ? 64 : 63) : 32;   // inclusive

    for (int c = tid; c < MT * 16; c += 256) {
        int r = c >> 4, cc = c & 15;
        *(uint4*)&As[r * SPAD + cc * 8] =
            *(const uint4*)(g_znb + (size_t)(m0 + r) * DD + cc * 8);
    }

    uint32_t bbase[2];
    bbase[0] = (uint32_t)__cvta_generic_to_shared(&Bs[0][0]);
    bbase[1] = (uint32_t)__cvta_generic_to_shared(&Bs[1][0]);

    {
        const int j0 = ((I + dstart) & 127) * MT;
        #pragma unroll
        for (int p = 0; p < 4; ++p) {
            int c = tid + p * 256;                  // 1024 chunks
            int r = c >> 4, cc = c & 15;
            cp_async16(bbase[0] + (uint32_t)(r * SPAD + cc * 8) * 2,
                       g_znb + (size_t)(j0 + r) * DD + cc * 8);
        }
        cp_commit();
    }
    __syncthreads();   // As visible

    uint32_t areg[8][2][4];
    #pragma unroll
    for (int ks = 0; ks < 8; ++ks) {
        const int colb = ks * 16 + 2 * i4;
        #pragma unroll
        for (int mt = 0; mt < 2; ++mt) {
            const int r0 = wm * 32 + mt * 16;
            areg[ks][mt][0] = *(const uint32_t*)&As[(r0 + g) * SPAD + colb];
            areg[ks][mt][1] = *(const uint32_t*)&As[(r0 + g + 8) * SPAD + colb];
            areg[ks][mt][2] = *(const uint32_t*)&As[(r0 + g) * SPAD + colb + 8];
            areg[ks][mt][3] = *(const uint32_t*)&As[(r0 + g + 8) * SPAD + colb + 8];
        }
    }

    const int l8 = lane & 7;
    const int rowb = wn * 16 + ((lane >> 4) & 1) * 8 + l8;
    const int colo = ((lane >> 3) & 1) * 8;
    const uint32_t ldm_off = (uint32_t)(rowb * SPAD + colo) * 2;

    float acc[2][2] = {{0.f, 0.f}, {0.f, 0.f}};

    for (int d = dstart; d <= dend; ++d) {
        const int buf = (d - dstart) & 1;
        cp_wait<0>();
        __syncthreads();

        if (d + 1 <= dend) {
            const int j1 = ((I + d + 1) & 127) * MT;
            #pragma unroll
            for (int p = 0; p < 4; ++p) {
                int c = tid + p * 256;
                int r = c >> 4, cc = c & 15;
                cp_async16(bbase[buf ^ 1] + (uint32_t)(r * SPAD + cc * 8) * 2,
                           g_znb + (size_t)(j1 + r) * DD + cc * 8);
            }
            cp_commit();
        }

        float cf[2][2][4];
        #pragma unroll
        for (int mt = 0; mt < 2; ++mt)
            #pragma unroll
            for (int nt = 0; nt < 2; ++nt)
                #pragma unroll
                for (int q = 0; q < 4; ++q) cf[mt][nt][q] = 0.f;

        const uint32_t bb = bbase[buf] + ldm_off;
        #pragma unroll
        for (int ks = 0; ks < 8; ++ks) {
            uint32_t b0, b1, b2, b3;
            ldmx4(b0, b1, b2, b3, bb + (uint32_t)ks * 32);
            mma_bf16(cf[0][0], areg[ks][0], b0, b1);
            mma_bf16(cf[1][0], areg[ks][1], b0, b1);
            mma_bf16(cf[0][1], areg[ks][0], b2, b3);
            mma_bf16(cf[1][1], areg[ks][1], b2, b3);
        }

        const int j0 = ((I + d) & 127) * MT;
        if (d != 0) {
            float cs0[2] = {0.f, 0.f}, cs1[2] = {0.f, 0.f};
            #pragma unroll
            for (int mt = 0; mt < 2; ++mt)
                #pragma unroll
                for (int nt = 0; nt < 2; ++nt) {
                    float e0 = ex2f(fmaf(cf[mt][nt][0], C2, -C2));
                    float e1 = ex2f(fmaf(cf[mt][nt][1], C2, -C2));
                    float e2 = ex2f(fmaf(cf[mt][nt][2], C2, -C2));
                    float e3 = ex2f(fmaf(cf[mt][nt][3], C2, -C2));
                    acc[mt][0] += e0 + e1;
                    acc[mt][1] += e2 + e3;
                    cs0[nt] += e0 + e2;
                    cs1[nt] += e1 + e3;
                }
            #pragma unroll
            for (int nt = 0; nt < 2; ++nt) {
                #pragma unroll
                for (int o = 4; o <= 16; o <<= 1) {
                    cs0[nt] += __shfl_xor_sync(0xffffffffu, cs0[nt], o);
                    cs1[nt] += __shfl_xor_sync(0xffffffffu, cs1[nt], o);
                }
            }
            if (g == 0) {
                #pragma unroll
                for (int nt = 0; nt < 2; ++nt) {
                    const int C = wn * 16 + nt * 8 + 2 * i4;
                    float2 v = make_float2(cs0[nt], cs1[nt]);
                    *(float2*)&g_colh[wm][d - 1][j0 + C] = v;
                }
            }
        } else {
            #pragma unroll
            for (int mt = 0; mt < 2; ++mt) {
                const int R = m0 + wm * 32 + mt * 16 + g;
                #pragma unroll
                for (int nt = 0; nt < 2; ++nt) {
                    const int C = j0 + wn * 16 + nt * 8 + 2 * i4;
                    float e0 = (R     == C    ) ? 0.f : ex2f(fmaf(cf[mt][nt][0], C2, -C2));
                    float e1 = (R     == C + 1) ? 0.f : ex2f(fmaf(cf[mt][nt][1], C2, -C2));
                    float e2 = (R + 8 == C    ) ? 0.f : ex2f(fmaf(cf[mt][nt][2], C2, -C2));
                    float e3 = (R + 8 == C + 1) ? 0.f : ex2f(fmaf(cf[mt][nt][3], C2, -C2));
                    acc[mt][0] += e0 + e1;
                    acc[mt][1] += e2 + e3;
                }
            }
        }
    }

    __syncthreads();
    #pragma unroll
    for (int mt = 0; mt < 2; ++mt) {
        sp[wm * 32 + mt * 16 + g    ][wn * 4 + i4] = acc[mt][0];
        sp[wm * 32 + mt * 16 + g + 8][wn * 4 + i4] = acc[mt][1];
    }
    __syncthreads();
    if (tid < MT) {
        float s = 0.f;
        #pragma unroll
        for (int k = 0; k < 16; ++k) s += sp[tid][k];
        g_Srow2[h][m0 + tid] = s;
    }
}

// ---------------- kernel 3: assemble row sums, more blocks + full MLP --------
// 512 blocks x 256 threads; 16 rows/block; 16 slot-groups x 8 unrolled loads.
// slots: idx 0..125 -> (wm=idx&1, d=idx>>1); idx 126/127 -> g_colh[wm][63] (2nd half only)
__global__ void __launch_bounds__(256) k_final1() {
    __shared__ float sredf[16][16];
    const int tid = threadIdx.x;
    const int r = tid & 15;          // row within block (coalesced)
    const int q = tid >> 4;          // 0..15 (slot group)
    const int row = blockIdx.x * 16 + r;

    float s = 0.f;
    #pragma unroll
    for (int k = 0; k < 8; ++k) {
        int idx = q * 8 + k;         // 0..127
        int wm = idx & 1, d = idx >> 1;
        if (d < 63) s += g_colh[wm][d][row];
        else if (row >= NB) s += g_colh[wm][63][row];
    }
    if (q == 0) s += g_Srow2[0][row] + g_Srow2[1][row];
    sredf[q][r] = s;
    __syncthreads();

    if (tid < 16) {
        float S = 0.f;
        #pragma unroll
        for (int k = 0; k < 16; ++k) S += sredf[k][tid];
        int rw = blockIdx.x * 16 + tid;
        double t = 2.0 + (double)logf(S) - (double)g_pos[rw];
        #pragma unroll
        for (int o = 8; o; o >>= 1)
            t += __shfl_xor_sync(0x0000ffffu, t, o);
        if (tid == 0) g_part[blockIdx.x] = t;
    }
}

// ---------------- kernel 4: final combine ------------------------------------
__global__ void __launch_bounds__(32) k_final2(float* out) {
    int tid = threadIdx.x;
    double t = 0.0;
    #pragma unroll
    for (int k = 0; k < 16; ++k) t += g_part[tid + 32 * k];
    #pragma unroll
    for (int o = 16; o; o >>= 1)
        t += __shfl_xor_sync(0xffffffffu, t, o);
    if (tid == 0) out[0] = (float)(t / (double)NN);
}

extern "C" void kernel_launch(void* const* d_in, const int* in_sizes, int n_in,
                              void* d_out, int out_size) {
    const float* zi = (const float*)d_in[0];
    const float* zj = (const float*)d_in[1];
    float* out = (float*)d_out;
    (void)in_sizes; (void)n_in; (void)out_size;

    k_prep<<<NB / 8, 256>>>(zi, zj);
    k_simexp<<<256, 256>>>();
    k_final1<<<512, 256>>>();
    k_final2<<<1, 32>>>(out);
}